// round 1
// baseline (speedup 1.0000x reference)
#include <cuda_runtime.h>

// Problem constants (fixed shapes for InferenceNet_10118942949387)
#define BDIM 8
#define TDIM 8192
#define MROWS (BDIM * TDIM)   // 65536 rows
#define IDIM 256
#define HDIM 1024
#define ODIM 256
#define CDIM 128
#define OUT_ELEMS ((size_t)MROWS * ODIM)   // 16,777,216

// Scratch for the dense hidden activation h (written by encoder, masked in-place
// by the top-k kernel, consumed by the decoder). __device__ global per rules.
__device__ float g_h[(size_t)MROWS * HDIM];

// ---------------------------------------------------------------------------
// Encoder GEMM: h[r, c] = sum_k x[r, k] * W_enc[k, c]   (chained FMA, k ascending)
// then + b_enc[c]. Exclusion (mask_prev) is applied later in the top-k kernel.
// Tile: 128x128 per CTA, 256 threads, 8x8 per thread, k-panels of 8.
// Sequential k-order per accumulator is load-bearing: it matches Eigen's
// (XLA-CPU) chained-fma accumulation so top-k ranks match the reference.
// ---------------------------------------------------------------------------
__global__ __launch_bounds__(256) void enc_kernel(
    const float* __restrict__ x, const float* __restrict__ W,
    const float* __restrict__ bias) {
  __shared__ float As[8][132];
  __shared__ float Bs[8][132];
  const int tid = threadIdx.x;
  const int tx = tid & 15;        // 16 col-groups
  const int ty = tid >> 4;        // 16 row-groups
  const int row0 = blockIdx.y * 128;
  const int col0 = blockIdx.x * 128;

  float acc[8][8];
#pragma unroll
  for (int i = 0; i < 8; i++)
#pragma unroll
    for (int j = 0; j < 8; j++) acc[i][j] = 0.f;

  const int lm  = tid >> 1;           // 0..127 (row within tile for A load)
  const int lk  = (tid & 1) * 4;      // 0 or 4 (k offset for A load)
  const int lkc = tid >> 5;           // 0..7   (k row for B load)
  const int lc  = (tid & 31) * 4;     // 0..124 (col for B load)

  for (int k0 = 0; k0 < IDIM; k0 += 8) {
    float4 av = *(const float4*)(x + (size_t)(row0 + lm) * IDIM + k0 + lk);
    As[lk + 0][lm] = av.x;
    As[lk + 1][lm] = av.y;
    As[lk + 2][lm] = av.z;
    As[lk + 3][lm] = av.w;
    float4 bv = *(const float4*)(W + (size_t)(k0 + lkc) * HDIM + col0 + lc);
    *(float4*)&Bs[lkc][lc] = bv;
    __syncthreads();
#pragma unroll
    for (int kc = 0; kc < 8; kc++) {
      float a[8], b[8];
      float4 a0 = *(const float4*)&As[kc][ty * 8];
      float4 a1 = *(const float4*)&As[kc][ty * 8 + 4];
      a[0] = a0.x; a[1] = a0.y; a[2] = a0.z; a[3] = a0.w;
      a[4] = a1.x; a[5] = a1.y; a[6] = a1.z; a[7] = a1.w;
      float4 b0 = *(const float4*)&Bs[kc][tx * 8];
      float4 b1 = *(const float4*)&Bs[kc][tx * 8 + 4];
      b[0] = b0.x; b[1] = b0.y; b[2] = b0.z; b[3] = b0.w;
      b[4] = b1.x; b[5] = b1.y; b[6] = b1.z; b[7] = b1.w;
#pragma unroll
      for (int i = 0; i < 8; i++)
#pragma unroll
        for (int j = 0; j < 8; j++) acc[i][j] = fmaf(a[i], b[j], acc[i][j]);
    }
    __syncthreads();
  }

#pragma unroll
  for (int i = 0; i < 8; i++) {
    const int r = row0 + ty * 8 + i;
#pragma unroll
    for (int j = 0; j < 8; j += 4) {
      const int c = col0 + tx * 8 + j;
      float4 o;
      o.x = acc[i][j + 0] + bias[c + 0];
      o.y = acc[i][j + 1] + bias[c + 1];
      o.z = acc[i][j + 2] + bias[c + 2];
      o.w = acc[i][j + 3] + bias[c + 3];
      *(float4*)(g_h + (size_t)r * HDIM + c) = o;
    }
  }
}

// ---------------------------------------------------------------------------
// Top-k kernel: one CTA (256 threads) per row of 1024.
//  - applies mask_prev exclusion (h=0 where mask_prev>0), matching ref order
//  - energy e = h*h; 64-bit key = (float_bits(e) << 10) | (1023 - idx)
//    encodes jax.lax.top_k ordering exactly (value desc, index asc); all keys
//    distinct, so "key >= kth_key" selects exactly k elements with exact ties.
//  - threshold search: 2048-bin histogram on top 11 bits of e_bits + suffix
//    scan gives both boundary bins (k=128, k=256) in one data pass; boundary
//    bin candidates resolved by exact brute-force ranking (few per row).
//  - writes mask_new = mask_prev + top128 indicator (to d_out mask region)
//    and masked h (top-256 kept) in place into g_h for the decoder.
// ---------------------------------------------------------------------------
__global__ __launch_bounds__(256) void topk_kernel(
    const float* __restrict__ mprev, float* __restrict__ mask_out) {
  __shared__ unsigned int hist[2048];
  __shared__ unsigned long long cand[1024];
  __shared__ unsigned int wsum[8];
  __shared__ unsigned int s_bin[2];
  __shared__ unsigned int s_rem[2];
  __shared__ unsigned long long s_key[2];
  __shared__ unsigned int s_ncand;

  const int tid = threadIdx.x;
  const size_t row = blockIdx.x;
  float* hrow = g_h + row * HDIM;

  float4 hv  = ((const float4*)hrow)[tid];
  float4 mpv = ((const float4*)(mprev + row * HDIM))[tid];
  float v[4]  = {hv.x, hv.y, hv.z, hv.w};
  float mp[4] = {mpv.x, mpv.y, mpv.z, mpv.w};
  unsigned int u[4];
#pragma unroll
  for (int i = 0; i < 4; i++) {
    if (mp[i] > 0.f) v[i] = 0.f;         // hidden_exclude_activation
    float e = v[i] * v[i];               // energy (>= 0, bits monotonic)
    u[i] = __float_as_uint(e);
  }

  for (int i = tid; i < 2048; i += 256) hist[i] = 0;
  __syncthreads();
#pragma unroll
  for (int i = 0; i < 4; i++) atomicAdd(&hist[u[i] >> 21], 1u);
  __syncthreads();

  // Suffix sums SUF[b] = sum_{v>=b} hist[v], computed as inclusive scan of
  // the reversed array; each thread owns 8 reversed-contiguous bins.
  unsigned int lv[8];
  unsigned int lsum = 0;
#pragma unroll
  for (int i = 0; i < 8; i++) {
    lv[i] = hist[2047 - (tid * 8 + i)];
    lsum += lv[i];
  }
  unsigned int sc = lsum;
  const int lane = tid & 31, wid = tid >> 5;
#pragma unroll
  for (int o = 1; o < 32; o <<= 1) {
    unsigned int n = __shfl_up_sync(0xffffffffu, sc, o);
    if (lane >= o) sc += n;
  }
  if (lane == 31) wsum[wid] = sc;
  __syncthreads();
  if (wid == 0) {
    unsigned int ws = (lane < 8) ? wsum[lane] : 0u;
#pragma unroll
    for (int o = 1; o < 8; o <<= 1) {
      unsigned int n = __shfl_up_sync(0xffffffffu, ws, o);
      if (lane >= o) ws += n;
    }
    if (lane < 8) wsum[lane] = ws;
  }
  __syncthreads();
  unsigned int run = (sc - lsum) + ((wid > 0) ? wsum[wid - 1] : 0u);
  unsigned int suf[8];
#pragma unroll
  for (int i = 0; i < 8; i++) {
    run += lv[i];
    suf[i] = run;
    hist[2047 - (tid * 8 + i)] = run;   // hist[] now holds SUF (own bins only)
  }
  __syncthreads();

  // Boundary bins: SUF[b] >= k && SUF[b+1] < k  (unique, since cnt[b] > 0 there)
  const unsigned int kk0 = CDIM, kk1 = 2 * CDIM;
#pragma unroll
  for (int i = 0; i < 8; i++) {
    const int b = 2047 - (tid * 8 + i);
    const unsigned int S  = suf[i];
    const unsigned int Sn = (b == 2047) ? 0u : hist[b + 1];
    if (S >= kk0 && Sn < kk0) { s_bin[0] = (unsigned)b; s_rem[0] = kk0 - Sn; }
    if (S >= kk1 && Sn < kk1) { s_bin[1] = (unsigned)b; s_rem[1] = kk1 - Sn; }
  }
  __syncthreads();

  // Resolve exact kth 64-bit key per selection via brute-force rank among
  // the boundary-bin candidates (typically ~40, worst case 1024).
  for (int s = 0; s < 2; s++) {
    if (tid == 0) s_ncand = 0;
    __syncthreads();
    const unsigned int b = s_bin[s];
#pragma unroll
    for (int i = 0; i < 4; i++) {
      if ((u[i] >> 21) == b) {
        const unsigned int p = atomicAdd(&s_ncand, 1u);
        cand[p] = ((unsigned long long)u[i] << 10) |
                  (unsigned long long)(1023 - (tid * 4 + i));
      }
    }
    __syncthreads();
    const unsigned int n = s_ncand, rem = s_rem[s];
    for (unsigned int c = tid; c < n; c += 256) {
      const unsigned long long kc_ = cand[c];
      unsigned int r = 0;
      for (unsigned int j = 0; j < n; j++) r += (cand[j] > kc_) ? 1u : 0u;
      if (r == rem - 1u) s_key[s] = kc_;  // exactly one (keys distinct)
    }
    __syncthreads();
  }

  const unsigned long long k128 = s_key[0];
  const unsigned long long k256 = s_key[1];
  float4 ho, mo;
  float* hp = (float*)&ho;
  float* mq = (float*)&mo;
#pragma unroll
  for (int i = 0; i < 4; i++) {
    const unsigned long long key =
        ((unsigned long long)u[i] << 10) |
        (unsigned long long)(1023 - (tid * 4 + i));
    hp[i] = (key >= k256) ? v[i] : 0.f;                   // mask_cur_share keep
    mq[i] = mp[i] + ((key >= k128) ? 1.f : 0.f);          // mask_new
  }
  ((float4*)hrow)[tid] = ho;
  ((float4*)(mask_out + row * HDIM))[tid] = mo;
}

// ---------------------------------------------------------------------------
// Decoder GEMM: out = h_masked @ W_dec(+type select) + b_dec
// Dense fp32, K=1024, N=256. Same tiling as encoder, chained-k order.
// ---------------------------------------------------------------------------
__global__ __launch_bounds__(256) void dec_kernel(
    const float* __restrict__ Wself, const float* __restrict__ bself,
    const float* __restrict__ Wsrc,  const float* __restrict__ bsrc,
    const int* __restrict__ dtype, float* __restrict__ out) {
  __shared__ float As[8][132];
  __shared__ float Bs[8][132];
  const int dt = *dtype;
  const float* __restrict__ W    = (dt == 0) ? Wself : Wsrc;
  const float* __restrict__ bias = (dt == 0) ? bself : bsrc;

  const int tid = threadIdx.x;
  const int tx = tid & 15;
  const int ty = tid >> 4;
  const int row0 = blockIdx.y * 128;
  const int col0 = blockIdx.x * 128;

  float acc[8][8];
#pragma unroll
  for (int i = 0; i < 8; i++)
#pragma unroll
    for (int j = 0; j < 8; j++) acc[i][j] = 0.f;

  const int lm  = tid >> 1;
  const int lk  = (tid & 1) * 4;
  const int lkc = tid >> 5;
  const int lc  = (tid & 31) * 4;

  for (int k0 = 0; k0 < HDIM; k0 += 8) {
    float4 av = *(const float4*)(g_h + (size_t)(row0 + lm) * HDIM + k0 + lk);
    As[lk + 0][lm] = av.x;
    As[lk + 1][lm] = av.y;
    As[lk + 2][lm] = av.z;
    As[lk + 3][lm] = av.w;
    float4 bv = *(const float4*)(W + (size_t)(k0 + lkc) * ODIM + col0 + lc);
    *(float4*)&Bs[lkc][lc] = bv;
    __syncthreads();
#pragma unroll
    for (int kc = 0; kc < 8; kc++) {
      float a[8], b[8];
      float4 a0 = *(const float4*)&As[kc][ty * 8];
      float4 a1 = *(const float4*)&As[kc][ty * 8 + 4];
      a[0] = a0.x; a[1] = a0.y; a[2] = a0.z; a[3] = a0.w;
      a[4] = a1.x; a[5] = a1.y; a[6] = a1.z; a[7] = a1.w;
      float4 b0 = *(const float4*)&Bs[kc][tx * 8];
      float4 b1 = *(const float4*)&Bs[kc][tx * 8 + 4];
      b[0] = b0.x; b[1] = b0.y; b[2] = b0.z; b[3] = b0.w;
      b[4] = b1.x; b[5] = b1.y; b[6] = b1.z; b[7] = b1.w;
#pragma unroll
      for (int i = 0; i < 8; i++)
#pragma unroll
        for (int j = 0; j < 8; j++) acc[i][j] = fmaf(a[i], b[j], acc[i][j]);
    }
    __syncthreads();
  }

#pragma unroll
  for (int i = 0; i < 8; i++) {
    const int r = row0 + ty * 8 + i;
#pragma unroll
    for (int j = 0; j < 8; j += 4) {
      const int c = col0 + tx * 8 + j;
      float4 o;
      o.x = acc[i][j + 0] + bias[c + 0];
      o.y = acc[i][j + 1] + bias[c + 1];
      o.z = acc[i][j + 2] + bias[c + 2];
      o.w = acc[i][j + 3] + bias[c + 3];
      *(float4*)(out + (size_t)r * ODIM + c) = o;
    }
  }
}

// ---------------------------------------------------------------------------
// Inputs (metadata order): x, mask_prev, W_enc, b_enc, W_dec_self, b_dec_self,
// W_dec_src, b_dec_src, decoder_type.
// Output layout: [out (B*T*ODIM floats)] then [mask_new (B*T*HDIM floats)].
// ---------------------------------------------------------------------------
extern "C" void kernel_launch(void* const* d_in, const int* in_sizes, int n_in,
                              void* d_out, int out_size) {
  const float* x          = (const float*)d_in[0];
  const float* mask_prev  = (const float*)d_in[1];
  const float* W_enc      = (const float*)d_in[2];
  const float* b_enc      = (const float*)d_in[3];
  const float* W_dec_self = (const float*)d_in[4];
  const float* b_dec_self = (const float*)d_in[5];
  const float* W_dec_src  = (const float*)d_in[6];
  const float* b_dec_src  = (const float*)d_in[7];
  const int*   dtype      = (const int*)d_in[8];

  float* out      = (float*)d_out;
  float* mask_out = out + OUT_ELEMS;

  dim3 g1(HDIM / 128, MROWS / 128);   // (8, 512)
  enc_kernel<<<g1, 256>>>(x, W_enc, b_enc);

  topk_kernel<<<MROWS, 256>>>(mask_prev, mask_out);

  dim3 g3(ODIM / 128, MROWS / 128);   // (2, 512)
  dec_kernel<<<g3, 256>>>(W_dec_self, b_dec_self, W_dec_src, b_dec_src,
                          dtype, out);
}

// round 2
// speedup vs baseline: 1.4282x; 1.4282x over previous
#include <cuda_runtime.h>

// Problem constants (fixed shapes for InferenceNet_10118942949387)
#define BDIM 8
#define TDIM 8192
#define MROWS (BDIM * TDIM)   // 65536 rows
#define IDIM 256
#define HDIM 1024
#define ODIM 256
#define CDIM 128
#define OUT_ELEMS ((size_t)MROWS * ODIM)   // 16,777,216

// Scratch for the dense hidden activation h.
__device__ float g_h[(size_t)MROWS * HDIM];

// ---------------------------------------------------------------------------
// SGEMM: C[r,c] = sum_k A[r,k] * W[k,c] + bias[c]
// 128x128 tile, 256 threads, 8x8/thread in split 4+4 layout (conflict-free
// fragment loads), double-buffered smem (one __syncthreads per 8-k panel).
// Accumulation per output stays a sequential chained FMA over ascending k —
// identical numerics to round 1 (top-k rank safety).
// W/bias selected at runtime via `sel` (nullptr => W0/b0).
// ---------------------------------------------------------------------------
template <int KD, int ND>
__global__ __launch_bounds__(256) void gemm_kernel(
    const float* __restrict__ A,
    const float* __restrict__ W0, const float* __restrict__ b0,
    const float* __restrict__ W1, const float* __restrict__ b1,
    const int* __restrict__ sel, float* __restrict__ C) {
  __shared__ float As[2][8][132];
  __shared__ float Bs[2][8][132];

  const float* __restrict__ W;
  const float* __restrict__ bias;
  if (sel != nullptr && *sel != 0) { W = W1; bias = b1; }
  else                             { W = W0; bias = b0; }

  const int tid = threadIdx.x;
  const int tx = tid & 15;         // 16 col groups
  const int ty = tid >> 4;         // 16 row groups
  const int row0 = blockIdx.y * 128;
  const int col0 = blockIdx.x * 128;

  const int lm  = tid >> 1;        // A load: row within tile
  const int lk  = (tid & 1) * 4;   // A load: k offset
  const int lkc = tid >> 5;        // B load: k row
  const int lc  = (tid & 31) * 4;  // B load: col

  const float* aptr = A + (size_t)(row0 + lm) * KD + lk;
  const float* bptr = W + (size_t)lkc * ND + col0 + lc;

  float acc[8][8];
#pragma unroll
  for (int i = 0; i < 8; i++)
#pragma unroll
    for (int j = 0; j < 8; j++) acc[i][j] = 0.f;

  // preload panel 0
  float4 av = *(const float4*)aptr;
  float4 bv = *(const float4*)bptr;
  As[0][lk + 0][lm] = av.x;
  As[0][lk + 1][lm] = av.y;
  As[0][lk + 2][lm] = av.z;
  As[0][lk + 3][lm] = av.w;
  *(float4*)&Bs[0][lkc][lc] = bv;
  __syncthreads();

  int buf = 0;
  for (int k0 = 0; k0 < KD; k0 += 8) {
    const bool more = (k0 + 8 < KD);
    if (more) {
      av = *(const float4*)(aptr + k0 + 8);
      bv = *(const float4*)(bptr + (size_t)(k0 + 8) * ND);
    }
#pragma unroll
    for (int kc = 0; kc < 8; kc++) {
      float4 a0 = *(const float4*)&As[buf][kc][ty * 4];
      float4 a1 = *(const float4*)&As[buf][kc][64 + ty * 4];
      float4 bq0 = *(const float4*)&Bs[buf][kc][tx * 4];
      float4 bq1 = *(const float4*)&Bs[buf][kc][64 + tx * 4];
      float a[8] = {a0.x, a0.y, a0.z, a0.w, a1.x, a1.y, a1.z, a1.w};
      float b[8] = {bq0.x, bq0.y, bq0.z, bq0.w, bq1.x, bq1.y, bq1.z, bq1.w};
#pragma unroll
      for (int i = 0; i < 8; i++)
#pragma unroll
        for (int j = 0; j < 8; j++) acc[i][j] = fmaf(a[i], b[j], acc[i][j]);
    }
    if (more) {
      buf ^= 1;
      As[buf][lk + 0][lm] = av.x;
      As[buf][lk + 1][lm] = av.y;
      As[buf][lk + 2][lm] = av.z;
      As[buf][lk + 3][lm] = av.w;
      *(float4*)&Bs[buf][lkc][lc] = bv;
      __syncthreads();
    }
  }

#pragma unroll
  for (int i = 0; i < 8; i++) {
    const int r = row0 + ((i < 4) ? (ty * 4 + i) : (64 + ty * 4 + (i - 4)));
    const int c0 = col0 + tx * 4;
    const int c1 = col0 + 64 + tx * 4;
    float4 o0, o1;
    o0.x = acc[i][0] + bias[c0 + 0];
    o0.y = acc[i][1] + bias[c0 + 1];
    o0.z = acc[i][2] + bias[c0 + 2];
    o0.w = acc[i][3] + bias[c0 + 3];
    o1.x = acc[i][4] + bias[c1 + 0];
    o1.y = acc[i][5] + bias[c1 + 1];
    o1.z = acc[i][6] + bias[c1 + 2];
    o1.w = acc[i][7] + bias[c1 + 3];
    *(float4*)(C + (size_t)r * ND + c0) = o0;
    *(float4*)(C + (size_t)r * ND + c1) = o1;
  }
}

// ---------------------------------------------------------------------------
// Top-k, warp-per-row, fully warp-synchronous (no __syncthreads).
// Key = (float_bits(h^2) << 10) | (1023 - idx): exact jax.lax.top_k order
// (value desc, index asc), all keys distinct -> "key >= kth key" selects
// exactly k with exact tie semantics.
// Per warp: 1024-bin histogram on u>>21 (sign0|exp8|m2), suffix scan fused
// with boundary detection (start at warp-max bin, early exit at 256), one
// candidate-gather pass for both boundaries, exact rank among candidates.
// ---------------------------------------------------------------------------
#define TK_WARPS 8
#define TK_BINS 1024
#define TK_CAP 320

__global__ __launch_bounds__(256) void topk_kernel(
    const float* __restrict__ mprev, float* __restrict__ mask_out) {
  __shared__ unsigned int sh_hist[TK_WARPS][TK_BINS];
  __shared__ unsigned long long sh_cand[TK_WARPS][TK_CAP];
  __shared__ unsigned int sh_ctr[TK_WARPS][2];
  __shared__ unsigned long long sh_key[TK_WARPS][2];

  const int lane = threadIdx.x & 31;
  const int w = threadIdx.x >> 5;
  const size_t row = (size_t)blockIdx.x * TK_WARPS + w;
  float* hrow = g_h + row * HDIM;
  const float* mrow = mprev + row * HDIM;

  unsigned int* hst = sh_hist[w];
#pragma unroll
  for (int j = 0; j < TK_BINS / 32; j++) hst[j * 32 + lane] = 0;
  if (lane < 2) sh_ctr[w][lane] = 0;
  __syncwarp();

  // Pass 1: histogram + warp-max bin
  unsigned int maxbin = 0;
#pragma unroll
  for (int j = 0; j < 8; j++) {
    float4 hv = ((const float4*)hrow)[j * 32 + lane];
    float4 mv = ((const float4*)mrow)[j * 32 + lane];
    float v[4] = {hv.x, hv.y, hv.z, hv.w};
    float m[4] = {mv.x, mv.y, mv.z, mv.w};
#pragma unroll
    for (int i = 0; i < 4; i++) {
      float vv = (m[i] > 0.f) ? 0.f : v[i];
      unsigned int u = __float_as_uint(vv * vv);
      unsigned int b = u >> 21;
      atomicAdd(&hst[b], 1u);
      maxbin = max(maxbin, b);
    }
  }
#pragma unroll
  for (int o = 16; o > 0; o >>= 1)
    maxbin = max(maxbin, __shfl_xor_sync(0xffffffffu, maxbin, o));
  __syncwarp();

  // Suffix scan (bins descending) fused with boundary detection.
  unsigned int bin0 = 0, rem0 = 0, bin1 = 0, rem1 = 0;
  bool f0 = false, f1 = false;
  unsigned int carry = 0;
  const int jstart = (int)(TK_BINS - 1 - maxbin) >> 5;
  for (int j = jstart; j < TK_BINS / 32; j++) {
    const int b = TK_BINS - 1 - (j * 32 + lane);
    const unsigned int cnt = hst[b];
    unsigned int s = cnt;
#pragma unroll
    for (int o = 1; o < 32; o <<= 1) {
      unsigned int n = __shfl_up_sync(0xffffffffu, s, o);
      if (lane >= o) s += n;
    }
    const unsigned int S = carry + s;       // inclusive suffix count
    const unsigned int Sp = S - cnt;        // exclusive (strictly higher bins)
    if (cnt && S >= CDIM && Sp < CDIM)       { bin0 = b; rem0 = CDIM - Sp; f0 = true; }
    if (cnt && S >= 2 * CDIM && Sp < 2 * CDIM) { bin1 = b; rem1 = 2 * CDIM - Sp; f1 = true; }
    carry += __shfl_sync(0xffffffffu, s, 31);
    if (carry >= 2 * CDIM) break;
  }
  {
    unsigned int m0 = __ballot_sync(0xffffffffu, f0);
    int src = __ffs(m0) - 1;
    bin0 = __shfl_sync(0xffffffffu, bin0, src);
    rem0 = __shfl_sync(0xffffffffu, rem0, src);
    unsigned int m1 = __ballot_sync(0xffffffffu, f1);
    src = __ffs(m1) - 1;
    bin1 = __shfl_sync(0xffffffffu, bin1, src);
    rem1 = __shfl_sync(0xffffffffu, rem1, src);
  }
  const bool same_bin = (bin0 == bin1);

  // Pass 2: gather boundary-bin candidates (both bins, one pass).
#pragma unroll
  for (int j = 0; j < 8; j++) {
    float4 hv = ((const float4*)hrow)[j * 32 + lane];
    float4 mv = ((const float4*)mrow)[j * 32 + lane];
    float v[4] = {hv.x, hv.y, hv.z, hv.w};
    float m[4] = {mv.x, mv.y, mv.z, mv.w};
#pragma unroll
    for (int i = 0; i < 4; i++) {
      float vv = (m[i] > 0.f) ? 0.f : v[i];
      unsigned int u = __float_as_uint(vv * vv);
      unsigned int b = u >> 21;
      const int idx = (j * 32 + lane) * 4 + i;
      const unsigned long long key =
          ((unsigned long long)u << 10) | (unsigned long long)(1023 - idx);
      if (b == bin0) {
        unsigned int p = atomicAdd(&sh_ctr[w][0], 1u);
        if (p < TK_CAP) sh_cand[w][p] = key;
      } else if (!same_bin && b == bin1) {
        unsigned int p = atomicAdd(&sh_ctr[w][1], 1u);
        if (p < TK_CAP) sh_cand[w][TK_CAP - 1 - p] = key;
      }
    }
  }
  __syncwarp();
  const unsigned int n0 = sh_ctr[w][0];
  const unsigned int n1 = sh_ctr[w][1];

  // Exact rank selection (keys distinct => exactly one hit per target rank).
  for (unsigned int c = lane; c < n0; c += 32) {
    const unsigned long long kc_ = sh_cand[w][c];
    unsigned int r = 0;
    for (unsigned int q = 0; q < n0; q++) r += (sh_cand[w][q] > kc_) ? 1u : 0u;
    if (r == rem0 - 1u) sh_key[w][0] = kc_;
    if (same_bin && r == rem1 - 1u) sh_key[w][1] = kc_;
  }
  if (!same_bin) {
    for (unsigned int c = lane; c < n1; c += 32) {
      const unsigned long long kc_ = sh_cand[w][TK_CAP - 1 - c];
      unsigned int r = 0;
      for (unsigned int q = 0; q < n1; q++)
        r += (sh_cand[w][TK_CAP - 1 - q] > kc_) ? 1u : 0u;
      if (r == rem1 - 1u) sh_key[w][1] = kc_;
    }
  }
  __syncwarp();
  const unsigned long long k128 = sh_key[w][0];
  const unsigned long long k256 = sh_key[w][1];

  // Pass 3: write masked h (top-256 kept) and mask_new (mprev + top-128).
#pragma unroll
  for (int j = 0; j < 8; j++) {
    float4 hv = ((const float4*)hrow)[j * 32 + lane];
    float4 mv = ((const float4*)mrow)[j * 32 + lane];
    float v[4] = {hv.x, hv.y, hv.z, hv.w};
    float m[4] = {mv.x, mv.y, mv.z, mv.w};
    float4 ho, mo;
    float* hp = (float*)&ho;
    float* mq = (float*)&mo;
#pragma unroll
    for (int i = 0; i < 4; i++) {
      float vv = (m[i] > 0.f) ? 0.f : v[i];
      unsigned int u = __float_as_uint(vv * vv);
      const int idx = (j * 32 + lane) * 4 + i;
      const unsigned long long key =
          ((unsigned long long)u << 10) | (unsigned long long)(1023 - idx);
      hp[i] = (key >= k256) ? vv : 0.f;
      mq[i] = m[i] + ((key >= k128) ? 1.f : 0.f);
    }
    ((float4*)hrow)[j * 32 + lane] = ho;
    ((float4*)(mask_out + row * HDIM))[j * 32 + lane] = mo;
  }
}

// ---------------------------------------------------------------------------
// Inputs: x, mask_prev, W_enc, b_enc, W_dec_self, b_dec_self, W_dec_src,
// b_dec_src, decoder_type. Output: [out | mask_new].
// ---------------------------------------------------------------------------
extern "C" void kernel_launch(void* const* d_in, const int* in_sizes, int n_in,
                              void* d_out, int out_size) {
  const float* x          = (const float*)d_in[0];
  const float* mask_prev  = (const float*)d_in[1];
  const float* W_enc      = (const float*)d_in[2];
  const float* b_enc      = (const float*)d_in[3];
  const float* W_dec_self = (const float*)d_in[4];
  const float* b_dec_self = (const float*)d_in[5];
  const float* W_dec_src  = (const float*)d_in[6];
  const float* b_dec_src  = (const float*)d_in[7];
  const int*   dtype      = (const int*)d_in[8];

  float* out      = (float*)d_out;
  float* mask_out = out + OUT_ELEMS;
  float* h        = nullptr;
  cudaGetSymbolAddress((void**)&h, g_h);

  dim3 g1(HDIM / 128, MROWS / 128);   // (8, 512)
  gemm_kernel<IDIM, HDIM><<<g1, 256>>>(x, W_enc, b_enc, W_enc, b_enc,
                                       nullptr, h);

  topk_kernel<<<MROWS / TK_WARPS, 256>>>(mask_prev, mask_out);

  dim3 g3(ODIM / 128, MROWS / 128);   // (2, 512)
  gemm_kernel<HDIM, ODIM><<<g3, 256>>>(h, W_dec_self, b_dec_self,
                                       W_dec_src, b_dec_src, dtype, out);
}